// round 13
// baseline (speedup 1.0000x reference)
#include <cuda_runtime.h>
#include <cuda_fp16.h>
#include <math.h>
#include <stdint.h>

#define BB 8
#define HH 128
#define WW 128
#define CC 64

// ---------------- scratch (allocation-free rule) ----------------
__device__ __align__(16) __half g_xh[BB*HH*WW*CC];      // NHWC x fp16 (gather)
__device__ __align__(16) uint2  g_wfragB[9*8*4*32];     // mma B-fragments fp16
__device__ __align__(16) float4 g_coef[BB*HH*WW];       // (sin, cos, wr*r, wr)

// ---------------- smem layout of k_main (dynamic, bytes) ----------------
#define A_STRIDE 144
#define SM_A0   0
#define SM_A1   18432
#define SM_B0   36864          // [3][8192] triple-buffered B ring
#define SM_SSB  61440          // int4[2][128]
#define SM_SSW  65536          // uint2[2][128]
#define SMEM_REQ 67584

// ---------------- helpers ----------------
__device__ __forceinline__ uint32_t smem_u32(const void* p) {
    uint32_t a;
    asm("{ .reg .u64 t; cvta.to.shared.u64 t, %1; cvt.u32.u64 %0, t; }" : "=r"(a) : "l"(p));
    return a;
}
__device__ __forceinline__ void ldsm_x4(uint32_t* r, uint32_t addr) {
    asm volatile("ldmatrix.sync.aligned.m8n8.x4.shared.b16 {%0,%1,%2,%3}, [%4];"
                 : "=r"(r[0]), "=r"(r[1]), "=r"(r[2]), "=r"(r[3]) : "r"(addr));
}
__device__ __forceinline__ void mma16816(float* d, const uint32_t* a, uint2 b) {
    asm volatile(
        "mma.sync.aligned.m16n8k16.row.col.f32.f16.f16.f32 "
        "{%0,%1,%2,%3}, {%4,%5,%6,%7}, {%8,%9}, {%0,%1,%2,%3};"
        : "+f"(d[0]), "+f"(d[1]), "+f"(d[2]), "+f"(d[3])
        : "r"(a[0]), "r"(a[1]), "r"(a[2]), "r"(a[3]), "r"(b.x), "r"(b.y));
}
__device__ __forceinline__ void cp16(uint32_t smem_dst, const void* gsrc) {
    asm volatile("cp.async.ca.shared.global [%0], [%1], 16;"
                 :: "r"(smem_dst), "l"(gsrc) : "memory");
}
// packed fp32x2 FMA (Blackwell): d = a * b + d, componentwise
__device__ __forceinline__ void ffma2(uint64_t& d, uint64_t a, uint64_t b) {
    asm("fma.rn.f32x2 %0, %1, %2, %0;" : "+l"(d) : "l"(a), "l"(b));
}
__device__ __forceinline__ uint64_t pack2(float lo, float hi) {
    uint64_t r;
    asm("mov.b64 %0, {%1, %2};" : "=l"(r) : "f"(lo), "f"(hi));
    return r;
}
__device__ __forceinline__ void unpack2(uint64_t v, float& lo, float& hi) {
    asm("mov.b64 {%0, %1}, %2;" : "=f"(lo), "=f"(hi) : "l"(v));
}

// ---------------------------------------------------------------------------
// K1: fused weight prep + coef convs (shfl-stencil, FFMA2, dup-weight LDS)
//     + fp16 NHWC transpose
// CTA = one (b,h) row, 256 threads / 8 warps.
// Warp w = channels w*8..w*8+7; lane l = pixels 4l..4l+3.
// Per (ch, dy): 1 LDG.128 + 2 shfl + 6 LDS.128 + 24 FFMA2 + 3 mov64.
// ---------------------------------------------------------------------------
#define SXH2_STRIDE 136   // halves per channel row (8B-aligned stride)

__global__ void __launch_bounds__(256) k_xform(const float* __restrict__ x,
                                               const float* __restrict__ wmain,
                                               const float* __restrict__ wrot,
                                               const float* __restrict__ brot,
                                               const float* __restrict__ wstr,
                                               const float* __restrict__ bstr,
                                               const float* __restrict__ wwhl,
                                               const float* __restrict__ bwhl) {
    __shared__ ulonglong2 swcd01[CC * 9];                  // [(w0,w0),(w1,w1)] per (c,tap)
    __shared__ ulonglong2 swcd23[CC * 9];                  // [(w2,w2),(w3,w3)]
    __shared__ float4 red[8 * 128];                        // [warp][px] partials
    __shared__ __align__(16) __half sxh2[CC][SXH2_STRIDE]; // [c][px] staging

    const int t    = threadIdx.x;
    const int lane = t & 31;
    const int w    = t >> 5;
    const int bh   = blockIdx.x;
    const int b    = bh >> 7;
    const int h    = bh & 127;

    // ---- B-fragment prep slice (independent; before any sync) ----
    if (t < 36) {
        int idx = bh * 36 + t;
        int k = idx % 9;
        int c = (idx / 9) % CC;
        int o = idx / (9 * CC);
        float wv = wmain[idx];
        int j = o >> 3, lane_n = o & 7;
        int q = c >> 4, kk = c & 15;
        int reg = kk >> 3, r = kk & 7;
        int ln = lane_n * 4 + (r >> 1);
        int halfsel = r & 1;
        __half* dst = (__half*)g_wfragB;
        dst[(((size_t)(k * 8 + j) * 4 + q) * 32 + ln) * 4 + reg * 2 + halfsel] = __float2half(wv);
    }

    // ---- dup coef weights: swcd01/swcd23[c*9+tap] ----
    for (int i = t; i < CC * 9; i += 256) {
        int c = i / 9, tap = i - c * 9;
        float w0 = wrot[(0 * CC + c) * 9 + tap];
        float w1 = wrot[(1 * CC + c) * 9 + tap];
        float w2 = wstr[c * 9 + tap];
        float w3 = wwhl[c * 9 + tap];
        ulonglong2 d01, d23;
        d01.x = pack2(w0, w0); d01.y = pack2(w1, w1);
        d23.x = pack2(w2, w2); d23.y = pack2(w3, w3);
        swcd01[i] = d01;
        swcd23[i] = d23;
    }
    __syncthreads();

    // ---- stencil conv: acc[out][px-pair] ----
    uint64_t acc[4][2];
#pragma unroll
    for (int o = 0; o < 4; o++) { acc[o][0] = 0ull; acc[o][1] = 0ull; }

    const float* xb = x + (size_t)(b * CC + w * 8) * (HH * WW);
#pragma unroll
    for (int cc = 0; cc < 8; cc++) {
        int c = w * 8 + cc;
        const float* xc = xb + (size_t)cc * (HH * WW);
        const ulonglong2* w01p = swcd01 + c * 9;
        const ulonglong2* w23p = swcd23 + c * 9;
#pragma unroll
        for (int dy = 0; dy < 3; dy++) {
            int y = h + dy - 1;
            if ((unsigned)y >= HH) continue;   // warp-uniform
            float4 C = *(const float4*)(xc + y * WW + lane * 4);
            if (dy == 1) {
                uint32_t h01, h23;
                asm("cvt.rn.f16x2.f32 %0, %1, %2;" : "=r"(h01) : "f"(C.y), "f"(C.x));
                asm("cvt.rn.f16x2.f32 %0, %1, %2;" : "=r"(h23) : "f"(C.w), "f"(C.z));
                *(uint2*)&sxh2[c][lane * 4] = make_uint2(h01, h23);
            }
            float up = __shfl_up_sync(0xffffffffu, C.w, 1);
            float dn = __shfl_down_sync(0xffffffffu, C.x, 1);
            if (lane == 0)  up = 0.f;   // image left boundary
            if (lane == 31) dn = 0.f;   // image right boundary
            uint64_t x001 = pack2(C.x, C.y);   // center pair 01 (reg-pair move)
            uint64_t x023 = pack2(C.z, C.w);   // center pair 23
            uint64_t xm01 = pack2(up, C.x);    // left pair 01
            uint64_t mid  = pack2(C.y, C.z);   // left pair 23 == right pair 01
            uint64_t xp23 = pack2(C.w, dn);    // right pair 23
            ulonglong2 wA01 = w01p[dy * 3 + 0], wA23 = w23p[dy * 3 + 0];
            ulonglong2 wB01 = w01p[dy * 3 + 1], wB23 = w23p[dy * 3 + 1];
            ulonglong2 wC01 = w01p[dy * 3 + 2], wC23 = w23p[dy * 3 + 2];
            // left tap
            ffma2(acc[0][0], xm01, wA01.x); ffma2(acc[0][1], mid,  wA01.x);
            ffma2(acc[1][0], xm01, wA01.y); ffma2(acc[1][1], mid,  wA01.y);
            ffma2(acc[2][0], xm01, wA23.x); ffma2(acc[2][1], mid,  wA23.x);
            ffma2(acc[3][0], xm01, wA23.y); ffma2(acc[3][1], mid,  wA23.y);
            // center tap
            ffma2(acc[0][0], x001, wB01.x); ffma2(acc[0][1], x023, wB01.x);
            ffma2(acc[1][0], x001, wB01.y); ffma2(acc[1][1], x023, wB01.y);
            ffma2(acc[2][0], x001, wB23.x); ffma2(acc[2][1], x023, wB23.x);
            ffma2(acc[3][0], x001, wB23.y); ffma2(acc[3][1], x023, wB23.y);
            // right tap
            ffma2(acc[0][0], mid,  wC01.x); ffma2(acc[0][1], xp23, wC01.x);
            ffma2(acc[1][0], mid,  wC01.y); ffma2(acc[1][1], xp23, wC01.y);
            ffma2(acc[2][0], mid,  wC23.x); ffma2(acc[2][1], xp23, wC23.x);
            ffma2(acc[3][0], mid,  wC23.y); ffma2(acc[3][1], xp23, wC23.y);
        }
    }

    // ---- write per-warp partials ----
    {
        float e[4][4];   // [out][i]
#pragma unroll
        for (int o = 0; o < 4; o++) {
            unpack2(acc[o][0], e[o][0], e[o][1]);
            unpack2(acc[o][1], e[o][2], e[o][3]);
        }
        float4* redp = red + w * 128 + lane * 4;
#pragma unroll
        for (int i = 0; i < 4; i++)
            redp[i] = make_float4(e[0][i], e[1][i], e[2][i], e[3][i]);
    }
    __syncthreads();   // red + sxh2 complete

    if (t < 128) {
        float a0 = 0.f, a1 = 0.f, a2 = 0.f, a3 = 0.f;
#pragma unroll
        for (int ww = 0; ww < 8; ww++) {
            float4 u = red[ww * 128 + t];
            a0 += u.x; a1 += u.y; a2 += u.z; a3 += u.w;
        }
        float s = a0 + brot[0];
        float c = a1 + brot[1];
        float n = sqrtf(s * s + c * c + 1e-6f);
        s /= n; c /= n;
        float r  = tanhf(a2 + bstr[0]) * 1.25f + 1.75f;
        float wl = tanhf(a3 + bwhl[0]) * 1.0f + 2.0f;
        g_coef[bh * WW + t] = make_float4(s, c, wl * r, wl);
    }

    // ---- coalesced fp16 NHWC writeout: sxh2[c][px] -> g_xh[px][c] ----
    {
        __half* gdst = g_xh + (size_t)bh * WW * CC;
#pragma unroll
        for (int it = 0; it < 4; it++) {
            int idx = it * 256 + t;
            int px = idx >> 3, c8 = idx & 7;
            __half hv[8];
#pragma unroll
            for (int j = 0; j < 8; j++) hv[j] = sxh2[c8 * 8 + j][px];
            *(uint4*)(gdst + px * CC + c8 * 8) = *(uint4*)hv;
        }
    }
}

// ---------------------------------------------------------------------------
// K2: deform gather (fp16) + mma.sync GEMM  (frozen since R11)
// CTA = one (b,h) row (128 px), 512 threads / 16 warps, 2 CTAs/SM.
// ---------------------------------------------------------------------------
__global__ void __launch_bounds__(512, 2) k_main(float* __restrict__ out) {
    extern __shared__ __align__(16) char smc[];
    int4*  ssb = (int4*)(smc + SM_SSB);    // [2][128]
    uint2* ssw = (uint2*)(smc + SM_SSW);   // [2][128]

    const int t    = threadIdx.x;
    const int wid  = t >> 5;
    const int lane = t & 31;
    const int bh   = blockIdx.x;
    const int b    = bh >> 7;
    const int h    = bh & 127;
    const char* xhimg = (const char*)(g_xh + (size_t)b * HH * WW * CC);

    float4 cf;
    if (t < 128) cf = g_coef[bh * WW + t];

    auto coords = [&](int k, int bf) {
        if (t >= 128) return;
        int kd3 = (k * 11) >> 5;
        float ky = (float)(kd3 - 1);
        float kx = (float)(k - 3 * kd3 - 1);
        float o0 = ky * cf.z;
        float o1 = kx * cf.w;
        float py = (float)h + cf.y * o0 + cf.x * o1;
        float px = (float)t - cf.x * o0 + cf.y * o1;
        float yf = floorf(py), xf = floorf(px);
        float ly = py - yf, lx = px - xf;
        int y0 = (int)yf, x0 = (int)xf;
        int y1 = y0 + 1,  x1 = x0 + 1;
        float w00 = (1.f - ly) * (1.f - lx);
        float w01 = (1.f - ly) * lx;
        float w10 = ly * (1.f - lx);
        float w11 = ly * lx;
        float vy0 = (y0 >= 0 && y0 < HH) ? 1.f : 0.f;
        float vy1 = (y1 >= 0 && y1 < HH) ? 1.f : 0.f;
        float vx0 = (x0 >= 0 && x0 < WW) ? 1.f : 0.f;
        float vx1 = (x1 >= 0 && x1 < WW) ? 1.f : 0.f;
        w00 *= vy0 * vx0; w01 *= vy0 * vx1;
        w10 *= vy1 * vx0; w11 *= vy1 * vx1;
        int yc0 = min(max(y0, 0), HH - 1);
        int yc1 = min(max(y1, 0), HH - 1);
        int xc0 = min(max(x0, 0), WW - 1);
        int xc1 = min(max(x1, 0), WW - 1);
        int4 bs;   // BYTE offsets into fp16 image (row = 128 B)
        bs.x = (yc0 * WW + xc0) << 7;
        bs.y = (yc0 * WW + xc1) << 7;
        bs.z = (yc1 * WW + xc0) << 7;
        bs.w = (yc1 * WW + xc1) << 7;
        ssb[bf * 128 + t] = bs;
        uint32_t wlo, whi;
        asm("cvt.rn.f16x2.f32 %0, %1, %2;" : "=r"(wlo) : "f"(w01), "f"(w00));
        asm("cvt.rn.f16x2.f32 %0, %1, %2;" : "=r"(whi) : "f"(w11), "f"(w10));
        ssw[bf * 128 + t] = make_uint2(wlo, whi);
    };

    const uint32_t smB_u = smem_u32(smc + SM_B0);

    // prime: cp.async B(0) -> ring buf 0 (8 KB = 512 x 16 B)
    {
        const char* src = (const char*)g_wfragB;
        cp16(smB_u + t * 16, src + t * 16);
        asm volatile("cp.async.commit_group;" ::: "memory");
    }
    coords(0, 0);
    __syncthreads();   // ssb0/ssw0 ready

    const uint32_t smA_u = smem_u32(smc);
    const int m0    = (wid & 7) * 16;
    const int jbase = (wid >> 3) * 4;
    const uint32_t ldsm_lane_off = (uint32_t)((lane & 15)) * A_STRIDE + ((lane >> 4) << 4);

    float acc[4][4];
#pragma unroll
    for (int j = 0; j < 4; j++)
#pragma unroll
        for (int i = 0; i < 4; i++) acc[j][i] = 0.f;

    const int lc8  = t & 7;    // channel octet (16 B fp16)
    const int gg64 = t >> 3;   // 0..63
    int rb = 0;                // ring slot of B(k)

#pragma unroll 1
    for (int k = 0; k < 9; k++) {
        const int bf = k & 1;

        // ---- gather tap k (fp16) into A[bf]: 2 pixels/thread ----
        {
            const int4*  sbp = ssb + bf * 128;
            const uint2* swp = ssw + bf * 128;
            char* Ab = smc + (bf ? SM_A1 : SM_A0);
#pragma unroll
            for (int it = 0; it < 2; it++) {
                int p = it * 64 + gg64;
                int4  bs = sbp[p];
                uint2 wv = swp[p];
                uint32_t u00 = __byte_perm(wv.x, 0, 0x1010);
                uint32_t u01 = __byte_perm(wv.x, 0, 0x3232);
                uint32_t u10 = __byte_perm(wv.y, 0, 0x1010);
                uint32_t u11 = __byte_perm(wv.y, 0, 0x3232);
                __half2 H00 = *(__half2*)&u00, H01 = *(__half2*)&u01;
                __half2 H10 = *(__half2*)&u10, H11 = *(__half2*)&u11;
                uint4 v0 = *(const uint4*)(xhimg + bs.x + lc8 * 16);
                uint4 v1 = *(const uint4*)(xhimg + bs.y + lc8 * 16);
                uint4 v2 = *(const uint4*)(xhimg + bs.z + lc8 * 16);
                uint4 v3 = *(const uint4*)(xhimg + bs.w + lc8 * 16);
                uint4 gv;
                {
                    __half2 a;
                    a = __hmul2(*(__half2*)&v0.x, H00);
                    a = __hfma2(*(__half2*)&v1.x, H01, a);
                    a = __hfma2(*(__half2*)&v2.x, H10, a);
                    a = __hfma2(*(__half2*)&v3.x, H11, a);
                    gv.x = *(uint32_t*)&a;
                    a = __hmul2(*(__half2*)&v0.y, H00);
                    a = __hfma2(*(__half2*)&v1.y, H01, a);
                    a = __hfma2(*(__half2*)&v2.y, H10, a);
                    a = __hfma2(*(__half2*)&v3.y, H11, a);
                    gv.y = *(uint32_t*)&a;
                    a = __hmul2(*(__half2*)&v0.z, H00);
                    a = __hfma2(*(__half2*)&v1.z, H01, a);
                    a = __hfma2(*(__half2*)&v2.z, H10, a);
                    a = __hfma2(*(__half2*)&v3.z, H11, a);
                    gv.z = *(uint32_t*)&a;
                    a = __hmul2(*(__half2*)&v0.w, H00);
                    a = __hfma2(*(__half2*)&v1.w, H01, a);
                    a = __hfma2(*(__half2*)&v2.w, H10, a);
                    a = __hfma2(*(__half2*)&v3.w, H11, a);
                    gv.w = *(uint32_t*)&a;
                }
                *(uint4*)(Ab + p * A_STRIDE + lc8 * 16) = gv;
            }
        }

        // ---- coords for tap k+1 ----
        if (k < 8) coords(k + 1, bf ^ 1);

        // ---- cp.async B(k+1) into ring slot (rb+1)%3 ----
        if (k < 8) {
            int nb = rb + 1; if (nb == 3) nb = 0;
            const char* src = (const char*)(g_wfragB + (size_t)(k + 1) * 1024);
            cp16(smB_u + (uint32_t)nb * 8192 + t * 16, src + t * 16);
        }
        asm volatile("cp.async.commit_group;" ::: "memory");
        asm volatile("cp.async.wait_group 1;" ::: "memory");   // B(k) complete
        __syncthreads();   // A[bf] ready; everyone past MMA(k-1)

        // ---- tensor phase: 4 ldmatrix.x4 (A) + B LDS + 16 HMMA ----
        {
            const uint32_t abase = smA_u + (uint32_t)(bf ? SM_A1 : SM_A0) +
                                   (uint32_t)m0 * A_STRIDE + ldsm_lane_off;
            uint32_t a[4][4];
#pragma unroll
            for (int q = 0; q < 4; q++) ldsm_x4(a[q], abase + q * 32);
            const uint2* bp = (const uint2*)(smc + SM_B0 + rb * 8192) + lane;
#pragma unroll
            for (int jj = 0; jj < 4; jj++) {
                int j = jbase + jj;
                uint2 bfr[4];
#pragma unroll
                for (int q = 0; q < 4; q++) bfr[q] = bp[(j * 4 + q) * 32];
#pragma unroll
                for (int q = 0; q < 4; q++) mma16816(acc[jj], a[q], bfr[q]);
            }
        }
        rb = rb + 1; if (rb == 3) rb = 0;
    }

    // ===================== epilogue: smem-staged coalesced store =====================
    __syncthreads();
    {
        float* sout = (float*)smc;   // [64][132] floats = 33792 B (overlaps A)
        int pxa = m0 + (lane >> 2);
#pragma unroll
        for (int jj = 0; jj < 4; jj++) {
            int o = (jbase + jj) * 8 + (lane & 3) * 2;
            sout[o * 132 + pxa]           = acc[jj][0];
            sout[(o + 1) * 132 + pxa]     = acc[jj][1];
            sout[o * 132 + pxa + 8]       = acc[jj][2];
            sout[(o + 1) * 132 + pxa + 8] = acc[jj][3];
        }
        __syncthreads();
#pragma unroll
        for (int it = 0; it < 4; it++) {
            int idx = it * 512 + t;
            int o = idx >> 5, pxq = idx & 31;
            float4 vv = *(const float4*)(sout + o * 132 + pxq * 4);
            *(float4*)(out + ((size_t)(b * CC + o) * HH + h) * WW + pxq * 4) = vv;
        }
    }
}

// ---------------------------------------------------------------------------
extern "C" void kernel_launch(void* const* d_in, const int* in_sizes, int n_in,
                              void* d_out, int out_size) {
    const float* x     = (const float*)d_in[0];
    const float* wmain = (const float*)d_in[1];
    const float* wrot  = (const float*)d_in[2];
    const float* brot  = (const float*)d_in[3];
    const float* wstr  = (const float*)d_in[4];
    const float* bstr  = (const float*)d_in[5];
    const float* wwhl  = (const float*)d_in[6];
    const float* bwhl  = (const float*)d_in[7];
    float* out = (float*)d_out;

    cudaFuncSetAttribute(k_main, cudaFuncAttributeMaxDynamicSharedMemorySize, SMEM_REQ);

    k_xform<<<BB * HH, 256>>>(x, wmain, wrot, brot, wstr, bstr, wwhl, bwhl);
    k_main<<<BB * HH, 512, SMEM_REQ>>>(out);
}

// round 14
// speedup vs baseline: 1.0432x; 1.0432x over previous
#include <cuda_runtime.h>
#include <cuda_fp16.h>
#include <math.h>
#include <stdint.h>

#define BB 8
#define HH 128
#define WW 128
#define CC 64

// ---------------- scratch (allocation-free rule) ----------------
__device__ __align__(16) __half g_xh[BB*HH*WW*CC];      // NHWC x fp16 (gather)
__device__ __align__(16) uint2  g_wfragB[9*8*4*32];     // mma B-fragments fp16
__device__ __align__(16) float4 g_coef[BB*HH*WW];       // (sin, cos, wr*r, wr)

// ---------------- smem layout of k_main (dynamic, bytes) ----------------
#define A_STRIDE 144
#define SM_A0   0
#define SM_A1   18432
#define SM_B0   36864          // [3][8192] triple-buffered B ring
#define SM_SSB  61440          // int4[2][128]
#define SM_SSW  65536          // uint2[2][128]
#define SMEM_REQ 67584

// ---------------- helpers ----------------
__device__ __forceinline__ uint32_t smem_u32(const void* p) {
    uint32_t a;
    asm("{ .reg .u64 t; cvta.to.shared.u64 t, %1; cvt.u32.u64 %0, t; }" : "=r"(a) : "l"(p));
    return a;
}
__device__ __forceinline__ void ldsm_x4(uint32_t* r, uint32_t addr) {
    asm volatile("ldmatrix.sync.aligned.m8n8.x4.shared.b16 {%0,%1,%2,%3}, [%4];"
                 : "=r"(r[0]), "=r"(r[1]), "=r"(r[2]), "=r"(r[3]) : "r"(addr));
}
__device__ __forceinline__ void mma16816(float* d, const uint32_t* a, uint2 b) {
    asm volatile(
        "mma.sync.aligned.m16n8k16.row.col.f32.f16.f16.f32 "
        "{%0,%1,%2,%3}, {%4,%5,%6,%7}, {%8,%9}, {%0,%1,%2,%3};"
        : "+f"(d[0]), "+f"(d[1]), "+f"(d[2]), "+f"(d[3])
        : "r"(a[0]), "r"(a[1]), "r"(a[2]), "r"(a[3]), "r"(b.x), "r"(b.y));
}
__device__ __forceinline__ void cp16(uint32_t smem_dst, const void* gsrc) {
    asm volatile("cp.async.ca.shared.global [%0], [%1], 16;"
                 :: "r"(smem_dst), "l"(gsrc) : "memory");
}
// packed fp32x2 FMA (Blackwell): d = a * b + d, componentwise
__device__ __forceinline__ void ffma2(uint64_t& d, uint64_t a, uint64_t b) {
    asm("fma.rn.f32x2 %0, %1, %2, %0;" : "+l"(d) : "l"(a), "l"(b));
}
__device__ __forceinline__ uint64_t bcast2(float v) {
    uint64_t r;
    asm("mov.b64 %0, {%1, %1};" : "=l"(r) : "f"(v));
    return r;
}
__device__ __forceinline__ uint64_t pack2(float lo, float hi) {
    uint64_t r;
    asm("mov.b64 %0, {%1, %2};" : "=l"(r) : "f"(lo), "f"(hi));
    return r;
}
__device__ __forceinline__ void unpack2(uint64_t v, float& lo, float& hi) {
    asm("mov.b64 {%0, %1}, %2;" : "=f"(lo), "=f"(hi) : "l"(v));
}

// ---------------------------------------------------------------------------
// K1: fused weight prep + coef convs (shfl-stencil, FFMA2, output-paired)
//     + fp16 NHWC transpose
// CTA = one (b,h) row, 256 threads / 8 warps.
// Warp w = channels w*8..w*8+7; lane l = pixels 4l..4l+3.
// Weights pre-packed (w0,w1)/(w2,w3) in smem -> LDS.64 broadcast.
// Per (ch, dy): 1 LDG.128 + 2 shfl + 6 LDS.64 + 6 bcast + 24 FFMA2.
// ---------------------------------------------------------------------------
#define SXH2_STRIDE 136   // halves per channel row (8B-aligned stride)

__global__ void __launch_bounds__(256) k_xform(const float* __restrict__ x,
                                               const float* __restrict__ wmain,
                                               const float* __restrict__ wrot,
                                               const float* __restrict__ brot,
                                               const float* __restrict__ wstr,
                                               const float* __restrict__ bstr,
                                               const float* __restrict__ wwhl,
                                               const float* __restrict__ bwhl) {
    __shared__ uint64_t swp01[CC * 9];                     // (w0,w1) per (c,tap)
    __shared__ uint64_t swp23[CC * 9];                     // (w2,w3)
    __shared__ float4 red[8 * 128];                        // [warp][px] partials
    __shared__ __align__(16) __half sxh2[CC][SXH2_STRIDE]; // [c][px] staging

    const int t    = threadIdx.x;
    const int lane = t & 31;
    const int w    = t >> 5;
    const int bh   = blockIdx.x;
    const int b    = bh >> 7;
    const int h    = bh & 127;

    // ---- B-fragment prep slice (independent; before any sync) ----
    if (t < 36) {
        int idx = bh * 36 + t;
        int k = idx % 9;
        int c = (idx / 9) % CC;
        int o = idx / (9 * CC);
        float wv = wmain[idx];
        int j = o >> 3, lane_n = o & 7;
        int q = c >> 4, kk = c & 15;
        int reg = kk >> 3, r = kk & 7;
        int ln = lane_n * 4 + (r >> 1);
        int halfsel = r & 1;
        __half* dst = (__half*)g_wfragB;
        dst[(((size_t)(k * 8 + j) * 4 + q) * 32 + ln) * 4 + reg * 2 + halfsel] = __float2half(wv);
    }

    // ---- packed coef weights: swp01/swp23[c*9+tap] ----
    for (int i = t; i < CC * 9; i += 256) {
        int c = i / 9, tap = i - c * 9;
        swp01[i] = pack2(wrot[(0 * CC + c) * 9 + tap], wrot[(1 * CC + c) * 9 + tap]);
        swp23[i] = pack2(wstr[c * 9 + tap],            wwhl[c * 9 + tap]);
    }
    __syncthreads();

    // ---- stencil conv: acc[px][outpair], px = 4*lane + i ----
    uint64_t acc[4][2];
#pragma unroll
    for (int i = 0; i < 4; i++) { acc[i][0] = 0ull; acc[i][1] = 0ull; }

    const float* xb = x + (size_t)(b * CC + w * 8) * (HH * WW);
#pragma unroll
    for (int cc = 0; cc < 8; cc++) {
        int c = w * 8 + cc;
        const float* xc = xb + (size_t)cc * (HH * WW);
        const uint64_t* w01p = swp01 + c * 9;
        const uint64_t* w23p = swp23 + c * 9;
#pragma unroll
        for (int dy = 0; dy < 3; dy++) {
            int y = h + dy - 1;
            if ((unsigned)y >= HH) continue;   // warp-uniform
            float4 C = *(const float4*)(xc + y * WW + lane * 4);
            if (dy == 1) {
                uint32_t h01, h23;
                asm("cvt.rn.f16x2.f32 %0, %1, %2;" : "=r"(h01) : "f"(C.y), "f"(C.x));
                asm("cvt.rn.f16x2.f32 %0, %1, %2;" : "=r"(h23) : "f"(C.w), "f"(C.z));
                *(uint2*)&sxh2[c][lane * 4] = make_uint2(h01, h23);
            }
            float up = __shfl_up_sync(0xffffffffu, C.w, 1);
            float dn = __shfl_down_sync(0xffffffffu, C.x, 1);
            if (lane == 0)  up = 0.f;   // image left boundary
            if (lane == 31) dn = 0.f;   // image right boundary
            uint64_t bu = bcast2(up),  bx = bcast2(C.x), by = bcast2(C.y);
            uint64_t bz = bcast2(C.z), bw = bcast2(C.w), bd = bcast2(dn);
            uint64_t wA01 = w01p[dy * 3 + 0], wA23 = w23p[dy * 3 + 0];
            uint64_t wB01 = w01p[dy * 3 + 1], wB23 = w23p[dy * 3 + 1];
            uint64_t wC01 = w01p[dy * 3 + 2], wC23 = w23p[dy * 3 + 2];
            // left tap: px i uses value (i-1)
            ffma2(acc[0][0], bu, wA01); ffma2(acc[0][1], bu, wA23);
            ffma2(acc[1][0], bx, wA01); ffma2(acc[1][1], bx, wA23);
            ffma2(acc[2][0], by, wA01); ffma2(acc[2][1], by, wA23);
            ffma2(acc[3][0], bz, wA01); ffma2(acc[3][1], bz, wA23);
            // center tap
            ffma2(acc[0][0], bx, wB01); ffma2(acc[0][1], bx, wB23);
            ffma2(acc[1][0], by, wB01); ffma2(acc[1][1], by, wB23);
            ffma2(acc[2][0], bz, wB01); ffma2(acc[2][1], bz, wB23);
            ffma2(acc[3][0], bw, wB01); ffma2(acc[3][1], bw, wB23);
            // right tap
            ffma2(acc[0][0], by, wC01); ffma2(acc[0][1], by, wC23);
            ffma2(acc[1][0], bz, wC01); ffma2(acc[1][1], bz, wC23);
            ffma2(acc[2][0], bw, wC01); ffma2(acc[2][1], bw, wC23);
            ffma2(acc[3][0], bd, wC01); ffma2(acc[3][1], bd, wC23);
        }
    }

    // ---- write per-warp partials ----
    {
        float4* redp = red + w * 128 + lane * 4;
#pragma unroll
        for (int i = 0; i < 4; i++) {
            float a0, a1, a2, a3;
            unpack2(acc[i][0], a0, a1);
            unpack2(acc[i][1], a2, a3);
            redp[i] = make_float4(a0, a1, a2, a3);
        }
    }
    __syncthreads();   // red + sxh2 complete

    if (t < 128) {
        float a0 = 0.f, a1 = 0.f, a2 = 0.f, a3 = 0.f;
#pragma unroll
        for (int ww = 0; ww < 8; ww++) {
            float4 u = red[ww * 128 + t];
            a0 += u.x; a1 += u.y; a2 += u.z; a3 += u.w;
        }
        float s = a0 + brot[0];
        float c = a1 + brot[1];
        float n = sqrtf(s * s + c * c + 1e-6f);
        s /= n; c /= n;
        float r  = tanhf(a2 + bstr[0]) * 1.25f + 1.75f;
        float wl = tanhf(a3 + bwhl[0]) * 1.0f + 2.0f;
        g_coef[bh * WW + t] = make_float4(s, c, wl * r, wl);
    }

    // ---- coalesced fp16 NHWC writeout: sxh2[c][px] -> g_xh[px][c] ----
    {
        __half* gdst = g_xh + (size_t)bh * WW * CC;
#pragma unroll
        for (int it = 0; it < 4; it++) {
            int idx = it * 256 + t;
            int px = idx >> 3, c8 = idx & 7;
            __half hv[8];
#pragma unroll
            for (int j = 0; j < 8; j++) hv[j] = sxh2[c8 * 8 + j][px];
            *(uint4*)(gdst + px * CC + c8 * 8) = *(uint4*)hv;
        }
    }
}

// ---------------------------------------------------------------------------
// K2: deform gather (fp16) + mma.sync GEMM  (frozen since R11)
// CTA = one (b,h) row (128 px), 512 threads / 16 warps, 2 CTAs/SM.
// ---------------------------------------------------------------------------
__global__ void __launch_bounds__(512, 2) k_main(float* __restrict__ out) {
    extern __shared__ __align__(16) char smc[];
    int4*  ssb = (int4*)(smc + SM_SSB);    // [2][128]
    uint2* ssw = (uint2*)(smc + SM_SSW);   // [2][128]

    const int t    = threadIdx.x;
    const int wid  = t >> 5;
    const int lane = t & 31;
    const int bh   = blockIdx.x;
    const int b    = bh >> 7;
    const int h    = bh & 127;
    const char* xhimg = (const char*)(g_xh + (size_t)b * HH * WW * CC);

    float4 cf;
    if (t < 128) cf = g_coef[bh * WW + t];

    auto coords = [&](int k, int bf) {
        if (t >= 128) return;
        int kd3 = (k * 11) >> 5;
        float ky = (float)(kd3 - 1);
        float kx = (float)(k - 3 * kd3 - 1);
        float o0 = ky * cf.z;
        float o1 = kx * cf.w;
        float py = (float)h + cf.y * o0 + cf.x * o1;
        float px = (float)t - cf.x * o0 + cf.y * o1;
        float yf = floorf(py), xf = floorf(px);
        float ly = py - yf, lx = px - xf;
        int y0 = (int)yf, x0 = (int)xf;
        int y1 = y0 + 1,  x1 = x0 + 1;
        float w00 = (1.f - ly) * (1.f - lx);
        float w01 = (1.f - ly) * lx;
        float w10 = ly * (1.f - lx);
        float w11 = ly * lx;
        float vy0 = (y0 >= 0 && y0 < HH) ? 1.f : 0.f;
        float vy1 = (y1 >= 0 && y1 < HH) ? 1.f : 0.f;
        float vx0 = (x0 >= 0 && x0 < WW) ? 1.f : 0.f;
        float vx1 = (x1 >= 0 && x1 < WW) ? 1.f : 0.f;
        w00 *= vy0 * vx0; w01 *= vy0 * vx1;
        w10 *= vy1 * vx0; w11 *= vy1 * vx1;
        int yc0 = min(max(y0, 0), HH - 1);
        int yc1 = min(max(y1, 0), HH - 1);
        int xc0 = min(max(x0, 0), WW - 1);
        int xc1 = min(max(x1, 0), WW - 1);
        int4 bs;   // BYTE offsets into fp16 image (row = 128 B)
        bs.x = (yc0 * WW + xc0) << 7;
        bs.y = (yc0 * WW + xc1) << 7;
        bs.z = (yc1 * WW + xc0) << 7;
        bs.w = (yc1 * WW + xc1) << 7;
        ssb[bf * 128 + t] = bs;
        uint32_t wlo, whi;
        asm("cvt.rn.f16x2.f32 %0, %1, %2;" : "=r"(wlo) : "f"(w01), "f"(w00));
        asm("cvt.rn.f16x2.f32 %0, %1, %2;" : "=r"(whi) : "f"(w11), "f"(w10));
        ssw[bf * 128 + t] = make_uint2(wlo, whi);
    };

    const uint32_t smB_u = smem_u32(smc + SM_B0);

    // prime: cp.async B(0) -> ring buf 0 (8 KB = 512 x 16 B)
    {
        const char* src = (const char*)g_wfragB;
        cp16(smB_u + t * 16, src + t * 16);
        asm volatile("cp.async.commit_group;" ::: "memory");
    }
    coords(0, 0);
    __syncthreads();   // ssb0/ssw0 ready

    const uint32_t smA_u = smem_u32(smc);
    const int m0    = (wid & 7) * 16;
    const int jbase = (wid >> 3) * 4;
    const uint32_t ldsm_lane_off = (uint32_t)((lane & 15)) * A_STRIDE + ((lane >> 4) << 4);

    float acc[4][4];
#pragma unroll
    for (int j = 0; j < 4; j++)
#pragma unroll
        for (int i = 0; i < 4; i++) acc[j][i] = 0.f;

    const int lc8  = t & 7;    // channel octet (16 B fp16)
    const int gg64 = t >> 3;   // 0..63
    int rb = 0;                // ring slot of B(k)

#pragma unroll 1
    for (int k = 0; k < 9; k++) {
        const int bf = k & 1;

        // ---- gather tap k (fp16) into A[bf]: 2 pixels/thread ----
        {
            const int4*  sbp = ssb + bf * 128;
            const uint2* swp = ssw + bf * 128;
            char* Ab = smc + (bf ? SM_A1 : SM_A0);
#pragma unroll
            for (int it = 0; it < 2; it++) {
                int p = it * 64 + gg64;
                int4  bs = sbp[p];
                uint2 wv = swp[p];
                uint32_t u00 = __byte_perm(wv.x, 0, 0x1010);
                uint32_t u01 = __byte_perm(wv.x, 0, 0x3232);
                uint32_t u10 = __byte_perm(wv.y, 0, 0x1010);
                uint32_t u11 = __byte_perm(wv.y, 0, 0x3232);
                __half2 H00 = *(__half2*)&u00, H01 = *(__half2*)&u01;
                __half2 H10 = *(__half2*)&u10, H11 = *(__half2*)&u11;
                uint4 v0 = *(const uint4*)(xhimg + bs.x + lc8 * 16);
                uint4 v1 = *(const uint4*)(xhimg + bs.y + lc8 * 16);
                uint4 v2 = *(const uint4*)(xhimg + bs.z + lc8 * 16);
                uint4 v3 = *(const uint4*)(xhimg + bs.w + lc8 * 16);
                uint4 gv;
                {
                    __half2 a;
                    a = __hmul2(*(__half2*)&v0.x, H00);
                    a = __hfma2(*(__half2*)&v1.x, H01, a);
                    a = __hfma2(*(__half2*)&v2.x, H10, a);
                    a = __hfma2(*(__half2*)&v3.x, H11, a);
                    gv.x = *(uint32_t*)&a;
                    a = __hmul2(*(__half2*)&v0.y, H00);
                    a = __hfma2(*(__half2*)&v1.y, H01, a);
                    a = __hfma2(*(__half2*)&v2.y, H10, a);
                    a = __hfma2(*(__half2*)&v3.y, H11, a);
                    gv.y = *(uint32_t*)&a;
                    a = __hmul2(*(__half2*)&v0.z, H00);
                    a = __hfma2(*(__half2*)&v1.z, H01, a);
                    a = __hfma2(*(__half2*)&v2.z, H10, a);
                    a = __hfma2(*(__half2*)&v3.z, H11, a);
                    gv.z = *(uint32_t*)&a;
                    a = __hmul2(*(__half2*)&v0.w, H00);
                    a = __hfma2(*(__half2*)&v1.w, H01, a);
                    a = __hfma2(*(__half2*)&v2.w, H10, a);
                    a = __hfma2(*(__half2*)&v3.w, H11, a);
                    gv.w = *(uint32_t*)&a;
                }
                *(uint4*)(Ab + p * A_STRIDE + lc8 * 16) = gv;
            }
        }

        // ---- coords for tap k+1 ----
        if (k < 8) coords(k + 1, bf ^ 1);

        // ---- cp.async B(k+1) into ring slot (rb+1)%3 ----
        if (k < 8) {
            int nb = rb + 1; if (nb == 3) nb = 0;
            const char* src = (const char*)(g_wfragB + (size_t)(k + 1) * 1024);
            cp16(smB_u + (uint32_t)nb * 8192 + t * 16, src + t * 16);
        }
        asm volatile("cp.async.commit_group;" ::: "memory");
        asm volatile("cp.async.wait_group 1;" ::: "memory");   // B(k) complete
        __syncthreads();   // A[bf] ready; everyone past MMA(k-1)

        // ---- tensor phase: 4 ldmatrix.x4 (A) + B LDS + 16 HMMA ----
        {
            const uint32_t abase = smA_u + (uint32_t)(bf ? SM_A1 : SM_A0) +
                                   (uint32_t)m0 * A_STRIDE + ldsm_lane_off;
            uint32_t a[4][4];
#pragma unroll
            for (int q = 0; q < 4; q++) ldsm_x4(a[q], abase + q * 32);
            const uint2* bp = (const uint2*)(smc + SM_B0 + rb * 8192) + lane;
#pragma unroll
            for (int jj = 0; jj < 4; jj++) {
                int j = jbase + jj;
                uint2 bfr[4];
#pragma unroll
                for (int q = 0; q < 4; q++) bfr[q] = bp[(j * 4 + q) * 32];
#pragma unroll
                for (int q = 0; q < 4; q++) mma16816(acc[jj], a[q], bfr[q]);
            }
        }
        rb = rb + 1; if (rb == 3) rb = 0;
    }

    // ===================== epilogue: smem-staged coalesced store =====================
    __syncthreads();
    {
        float* sout = (float*)smc;   // [64][132] floats = 33792 B (overlaps A)
        int pxa = m0 + (lane >> 2);
#pragma unroll
        for (int jj = 0; jj < 4; jj++) {
            int o = (jbase + jj) * 8 + (lane & 3) * 2;
            sout[o * 132 + pxa]           = acc[jj][0];
            sout[(o + 1) * 132 + pxa]     = acc[jj][1];
            sout[o * 132 + pxa + 8]       = acc[jj][2];
            sout[(o + 1) * 132 + pxa + 8] = acc[jj][3];
        }
        __syncthreads();
#pragma unroll
        for (int it = 0; it < 4; it++) {
            int idx = it * 512 + t;
            int o = idx >> 5, pxq = idx & 31;
            float4 vv = *(const float4*)(sout + o * 132 + pxq * 4);
            *(float4*)(out + ((size_t)(b * CC + o) * HH + h) * WW + pxq * 4) = vv;
        }
    }
}

// ---------------------------------------------------------------------------
extern "C" void kernel_launch(void* const* d_in, const int* in_sizes, int n_in,
                              void* d_out, int out_size) {
    const float* x     = (const float*)d_in[0];
    const float* wmain = (const float*)d_in[1];
    const float* wrot  = (const float*)d_in[2];
    const float* brot  = (const float*)d_in[3];
    const float* wstr  = (const float*)d_in[4];
    const float* bstr  = (const float*)d_in[5];
    const float* wwhl  = (const float*)d_in[6];
    const float* bwhl  = (const float*)d_in[7];
    float* out = (float*)d_out;

    cudaFuncSetAttribute(k_main, cudaFuncAttributeMaxDynamicSharedMemorySize, SMEM_REQ);

    k_xform<<<BB * HH, 256>>>(x, wmain, wrot, brot, wstr, bstr, wwhl, bwhl);
    k_main<<<BB * HH, 512, SMEM_REQ>>>(out);
}